// round 17
// baseline (speedup 1.0000x reference)
#include <cuda_runtime.h>
#include <cuda_fp16.h>
#include <mma.h>
#include <math.h>
using namespace nvcuda;

#define Bz   32
#define Nn   512
#define LITD 64
#define SEMD 64
#define Hh   64
#define Ee   128
#define G3H  192
#define OUTD 64
#define MAXD 128

typedef unsigned long long ull;

// ---------------- packed fp32x2 helpers ----------------------------------
__device__ __forceinline__ ull pk2(float x, float y) {
    union { float2 f; ull u; } t; t.f = make_float2(x, y); return t.u;
}
__device__ __forceinline__ float2 upk2(ull u) {
    union { float2 f; ull u; } t; t.u = u; return t.f;
}
__device__ __forceinline__ void ffma2(ull& d, ull a, ull b) {
    asm("fma.rn.f32x2 %0, %1, %2, %0;" : "+l"(d) : "l"(a), "l"(b));
}

// ---------------- device scratch (static, no allocations) ----------------
__device__ float  g_xp [2u*Bz*Nn*G3H];
__device__ float  g_chA[4u*Bz*Nn*Ee];
__device__ float  g_chB[4u*Bz*Nn*Ee];
__device__ __half g_whAh[4u*Bz*Nn*Ee];
__device__ __half g_whBh[4u*Bz*Nn*Ee];
__device__ __half g_Wgh[Ee*Ee];
__device__ __half g_ghwh[4u*Bz*Nn*Ee];
__device__ float  g_ah1[4u*Bz*Nn];
__device__ float  g_ah2[4u*Bz*Nn];
__device__ short  g_adj[4u*Bz*Nn*MAXD];
__device__ int    g_cnt[4u*Bz*Nn];
__device__ unsigned g_bits[2u*Bz*Nn*(Nn/32)];   // adjacency bit-matrix
__device__ float  g_part[2u*Bz*8*Ee];
__device__ float  g_emb[2u*Bz*OUTD];

// ---------------- Wg fp32 -> fp16 ----------------------------------------
__global__ void k_prep(const float* __restrict__ Wg)
{
    int i = blockIdx.x * 1024 + threadIdx.x;
    if (i < Ee * Ee) g_Wgh[i] = __float2half(Wg[i]);
}

// ---------------- fwd builder + bitmap ------------------------------------
__global__ void k_build_fwd(const float* __restrict__ A1,
                            const float* __restrict__ A2)
{
    int g = blockIdx.z;
    const float* A = g ? A2 : A1;
    int b = blockIdx.y;
    int w = threadIdx.x >> 5, lane = threadIdx.x & 31;
    int row = blockIdx.x * 8 + w;
    int v = g * 2;
    const float* Ar = A + ((size_t)b * Nn + row) * Nn;
    short* out = g_adj + (((size_t)v * Bz + b) * Nn + row) * MAXD;
    unsigned* bits = g_bits + (((size_t)g * Bz + b) * Nn + row) * (Nn / 32);
    int cnt = 0;
    for (int j0 = 0; j0 < Nn; j0 += 32) {
        float val = Ar[j0 + lane];
        unsigned m = __ballot_sync(0xffffffffu, val > 0.5f);
        if (val > 0.5f) {
            int pos = cnt + __popc(m & ((1u << lane) - 1u));
            if (pos < MAXD) out[pos] = (short)(j0 + lane);
        }
        if (lane == 0) bits[j0 >> 5] = m;
        cnt += __popc(m);
    }
    if (lane == 0) g_cnt[((size_t)v * Bz + b) * Nn + row] = cnt < MAXD ? cnt : MAXD;
}

// ---------------- rev builder from bitmap (broadcast reads) ---------------
__global__ void k_build_rev()
{
    int g = blockIdx.z;
    int b = blockIdx.y;
    int w = threadIdx.x >> 5, lane = threadIdx.x & 31;
    int jw = blockIdx.x * 8 + w;                 // word index 0..15
    int j = jw * 32 + lane;
    int v = g * 2 + 1;
    const unsigned* W = g_bits + ((size_t)g * Bz + b) * Nn * (Nn / 32);
    short* out = g_adj + (((size_t)v * Bz + b) * Nn + j) * MAXD;
    unsigned mybit = 1u << lane;
    int cnt = 0;
#pragma unroll 8
    for (int i = 0; i < Nn; i++) {
        unsigned word = W[(size_t)i * (Nn / 32) + jw];   // broadcast per warp
        if ((word & mybit) && cnt < MAXD) out[cnt++] = (short)i;
    }
    g_cnt[((size_t)v * Bz + b) * Nn + j] = cnt;
}

// ---------------- literal path: relu(lit @ Wl), 32 nodes/block -----------
__global__ void __launch_bounds__(256)
k_lit(const float* __restrict__ L1, const float* __restrict__ L2,
      const float* __restrict__ Wl1, const float* __restrict__ Wl2)
{
    int g = blockIdx.z, b = blockIdx.y, n0 = blockIdx.x * 32;
    const float* L  = (g ? L2 : L1) + ((size_t)b * Nn + n0) * LITD;
    const float* Wl = g ? Wl2 : Wl1;
    __shared__ __align__(16) float ls[32 * 64];
    int tid = threadIdx.x;
    for (int idx = tid; idx < 32 * 64; idx += 256) ls[idx] = L[idx];
    int col = tid & 63, q = tid >> 6;
    ull wl2[32];
#pragma unroll
    for (int i = 0; i < 32; i++)
        wl2[i] = pk2(__ldg(&Wl[(2 * i) * 64 + col]), __ldg(&Wl[(2 * i + 1) * 64 + col]));
    __syncthreads();
    {
        ull acc[8];
#pragma unroll
        for (int nn = 0; nn < 8; nn++) acc[nn] = pk2(0.f, 0.f);
#pragma unroll
        for (int kq = 0; kq < 16; kq++) {
#pragma unroll
            for (int nn = 0; nn < 8; nn++) {
                float4 s4 = *(const float4*)(ls + (q * 8 + nn) * 64 + 4 * kq);
                ffma2(acc[nn], pk2(s4.x, s4.y), wl2[2 * kq]);
                ffma2(acc[nn], pk2(s4.z, s4.w), wl2[2 * kq + 1]);
            }
        }
#pragma unroll
        for (int nn = 0; nn < 8; nn++) {
            float2 f = upk2(acc[nn]);
            float r = fmaxf(f.x + f.y, 0.f);
            int node = n0 + q * 8 + nn;
            size_t iF = (((size_t)(2 * g)     * Bz + b) * Nn + node) * Ee + col;
            size_t iR = (((size_t)(2 * g + 1) * Bz + b) * Nn + node) * Ee + col;
            g_chA[iF] = r;  g_chA[iR] = r;
            __half rh = __float2half(r);
            g_whAh[iF] = rh; g_whAh[iR] = rh;
        }
    }
}

// ---------------- GRU input projection, 32 nodes/block -------------------
__global__ void __launch_bounds__(192)
k_xp(const float* __restrict__ S1, const float* __restrict__ S2,
     const float* __restrict__ K1, const float* __restrict__ K2,
     const float* __restrict__ B1, const float* __restrict__ B2)
{
    int g = blockIdx.z, b = blockIdx.y, n0 = blockIdx.x * 32;
    const float* S  = (g ? S2 : S1) + ((size_t)b * Nn + n0) * SEMD;
    const float* Wk = g ? K2 : K1;
    const float* bb = g ? B2 : B1;
    __shared__ __align__(16) float ss[32 * 64];
    int tid = threadIdx.x;
    for (int idx = tid; idx < 32 * 64; idx += 192) ss[idx] = S[idx];
    int col = tid;
    ull wk2[32];
#pragma unroll
    for (int i = 0; i < 32; i++)
        wk2[i] = pk2(__ldg(&Wk[(2 * i) * G3H + col]), __ldg(&Wk[(2 * i + 1) * G3H + col]));
    float b0 = bb[col];
    __syncthreads();
    float* xp = g_xp + (((size_t)g * Bz + b) * Nn + n0) * G3H;
    for (int ngrp = 0; ngrp < 4; ngrp++) {
        ull acc[8];
#pragma unroll
        for (int nn = 0; nn < 8; nn++) acc[nn] = pk2(0.f, 0.f);
#pragma unroll
        for (int kq = 0; kq < 16; kq++) {
#pragma unroll
            for (int nn = 0; nn < 8; nn++) {
                float4 s4 = *(const float4*)(ss + (ngrp * 8 + nn) * 64 + 4 * kq);
                ffma2(acc[nn], pk2(s4.x, s4.y), wk2[2 * kq]);
                ffma2(acc[nn], pk2(s4.z, s4.w), wk2[2 * kq + 1]);
            }
        }
#pragma unroll
        for (int nn = 0; nn < 8; nn++) {
            float2 f = upk2(acc[nn]);
            xp[(size_t)(ngrp * 8 + nn) * G3H + col] = f.x + f.y + b0;
        }
    }
}

// ---------------- GRU scan (4-deep xp prefetch) ---------------------------
__global__ void __launch_bounds__(192, 1)
k_gru(const float* __restrict__ rk1, const float* __restrict__ rk2,
      const float* __restrict__ gb1, const float* __restrict__ gb2)
{
    int g = blockIdx.x >> 5;
    int b = blockIdx.x & 31;
    const float* rk = g ? rk2 : rk1;
    const float* gb = g ? gb2 : gb1;
    __shared__ __align__(16) float sm[12288];
    int tid = threadIdx.x;
    for (int idx = tid; idx < 64 * G3H; idx += 192) sm[idx] = rk[idx];
    __syncthreads();
    ull rk2p[32];
#pragma unroll
    for (int i = 0; i < 32; i++)
        rk2p[i] = pk2(sm[(2 * i) * G3H + tid], sm[(2 * i + 1) * G3H + tid]);
    __syncthreads();
    float* h_sh   = sm;
    float* pre_sh = sm + 64;
    float* rh_sh  = sm + 192;
    float* xh_sh  = sm + 256;
    if (tid < 64) h_sh[tid] = 0.f;
    float bb = gb[G3H + tid];
    const float* xp = g_xp + ((size_t)g * Bz + b) * Nn * G3H;
    size_t oF = (((size_t)(2 * g)     * Bz + b) * Nn) * Ee;
    size_t oR = (((size_t)(2 * g + 1) * Bz + b) * Nn) * Ee;
    __syncthreads();
    float xf[4];
#pragma unroll
    for (int d = 0; d < 4; d++) xf[d] = xp[(size_t)d * G3H + tid];
#pragma unroll 4
    for (int t = 0; t < Nn; t++) {
        float xv = xf[t & 3];
        if (t + 4 < Nn) xf[t & 3] = xp[(size_t)(t + 4) * G3H + tid];
        ull a0 = pk2(0.f, 0.f), a1 = a0, a2 = a0, a3 = a0;
#pragma unroll
        for (int q = 0; q < 32; q += 4) {
            ffma2(a0, *(const ull*)(h_sh + 2 * q),     rk2p[q]);
            ffma2(a1, *(const ull*)(h_sh + 2 * q + 2), rk2p[q + 1]);
            ffma2(a2, *(const ull*)(h_sh + 2 * q + 4), rk2p[q + 2]);
            ffma2(a3, *(const ull*)(h_sh + 2 * q + 6), rk2p[q + 3]);
        }
        float2 f0 = upk2(a0), f1 = upk2(a1), f2 = upk2(a2), f3 = upk2(a3);
        float pre = ((f0.x + f0.y) + (f1.x + f1.y)) + ((f2.x + f2.y) + (f3.x + f3.y)) + bb;
        if (tid < 128) pre_sh[tid] = xv + pre;
        else { rh_sh[tid - 128] = pre; xh_sh[tid - 128] = xv; }
        __syncthreads();
        if (tid < 64) {
            float z = 1.f / (1.f + __expf(-pre_sh[tid]));
            float r = 1.f / (1.f + __expf(-pre_sh[64 + tid]));
            float ag = xh_sh[tid] + r * rh_sh[tid];
            ag = fminf(fmaxf(ag, -12.f), 12.f);
            float e2 = __expf(-2.f * ag);
            float hh = (1.f - e2) / (1.f + e2);
            float hn = z * h_sh[tid] + (1.f - z) * hh;
            h_sh[tid] = hn;
            float rl = fmaxf(hn, 0.f);
            size_t off = (size_t)t * Ee + 64 + tid;
            g_chA[oF + off] = rl;  g_chA[oR + off] = rl;
            __half rh16 = __float2half(rl);
            g_whAh[oF + off] = rh16;  g_whAh[oR + off] = rh16;
        }
        __syncthreads();
    }
}

// ---------------- per-step transform: tensor-core GEMM -------------------
#define TLD 144
#define TR_SMEM ((64*TLD + 128*TLD) * 2)
__global__ void __launch_bounds__(256)
k_transform(int srcA,
            const float* __restrict__ a1w, const float* __restrict__ a1b,
            const float* __restrict__ a2w, const float* __restrict__ a2b)
{
    const __half* whh = srcA ? g_whAh : g_whBh;
    extern __shared__ __align__(16) __half dynh[];
    __half* A_sh = dynh;             // [64][TLD]
    __half* B_sh = dynh + 64 * TLD;  // [128][TLD]; reused as float C[64][128]
    __shared__ float av[256];
    int c = blockIdx.z, b = blockIdx.y, n0 = blockIdx.x * 64;
    size_t base = (((size_t)c * Bz + b) * Nn + n0) * Ee;
    int tid = threadIdx.x;
    if (tid < 128) av[tid] = a1w[tid];
    else           av[tid] = a2w[tid - 128];
    {
        int row = tid >> 2, part = tid & 3;
        const uint4* src = (const uint4*)(whh + base) + row * 16 + part * 4;
        uint4* dst = (uint4*)(A_sh + row * TLD + part * 32);
#pragma unroll
        for (int i = 0; i < 4; i++) dst[i] = src[i];
    }
    {
        int row = tid >> 1, part = tid & 1;
        const uint4* src = (const uint4*)g_Wgh + row * 16 + part * 8;
        uint4* dst = (uint4*)(B_sh + row * TLD + part * 64);
#pragma unroll
        for (int i = 0; i < 8; i++) dst[i] = src[i];
    }
    __syncthreads();

    int w = tid >> 5, lane = tid & 31;
    int mt = w >> 1, ct0 = (w & 1) * 4;
    wmma::fragment<wmma::accumulator, 16, 16, 16, float> acc[4];
#pragma unroll
    for (int j = 0; j < 4; j++) wmma::fill_fragment(acc[j], 0.f);
#pragma unroll
    for (int k = 0; k < 8; k++) {
        wmma::fragment<wmma::matrix_a, 16, 16, 16, __half, wmma::row_major> fa;
        wmma::load_matrix_sync(fa, A_sh + (mt * 16) * TLD + k * 16, TLD);
#pragma unroll
        for (int j = 0; j < 4; j++) {
            wmma::fragment<wmma::matrix_b, 16, 16, 16, __half, wmma::row_major> fb;
            wmma::load_matrix_sync(fb, B_sh + (k * 16) * TLD + (ct0 + j) * 16, TLD);
            wmma::mma_sync(acc[j], fa, fb, acc[j]);
        }
    }
    __syncthreads();
    float* Cf = (float*)B_sh;
#pragma unroll
    for (int j = 0; j < 4; j++)
        wmma::store_matrix_sync(Cf + (mt * 16) * 128 + (ct0 + j) * 16, acc[j],
                                128, wmma::mem_row_major);
    __syncthreads();
    {
        const float2* c2 = (const float2*)Cf;
        __half2* d2 = (__half2*)(g_ghwh + base);
        for (int i = tid; i < 64 * 128 / 2; i += 256)
            d2[i] = __float22half2_rn(c2[i]);
    }
#pragma unroll
    for (int ii = 0; ii < 8; ii++) {
        int node = w * 8 + ii;
        float x0 = __half2float(A_sh[node * TLD + lane]);
        float x1 = __half2float(A_sh[node * TLD + 64 + lane]);
        float s1 = x0 * av[lane]       + x1 * av[64 + lane];
        float s2 = x0 * av[128 + lane] + x1 * av[192 + lane];
#pragma unroll
        for (int off = 16; off; off >>= 1) {
            s1 += __shfl_xor_sync(0xffffffffu, s1, off);
            s2 += __shfl_xor_sync(0xffffffffu, s2, off);
        }
        if (lane == 0) {
            size_t idx = ((size_t)c * Bz + b) * Nn + n0 + node;
            g_ah1[idx] = s1 + a1b[0];
            g_ah2[idx] = s2 + a2b[0];
        }
    }
}

// ---------------- per-step attend: ghw staged in smem (fp16) -------------
#define ATT_SMEM (512*128*2 + 32*128*4 + 32*128*2)
__global__ void __launch_bounds__(1024)
k_attend(int srcA)
{
    const float* whc = srcA ? g_chA : g_chB;
    float*       whn = srcA ? g_chB : g_chA;
    __half*      whnh = srcA ? g_whBh : g_whAh;
    int c = blockIdx.y, b = blockIdx.x, half = blockIdx.z;
    size_t cb = ((size_t)c * Bz + b) * Nn;
    extern __shared__ __align__(16) char dyn[];
    __half* ghw_sh = (__half*)dyn;
    float*  p_all  = (float*)(dyn + 512 * 128 * 2);
    short*  nj_all = (short*)(dyn + 512 * 128 * 2 + 32 * 128 * 4);
    int tid = threadIdx.x, lane = tid & 31, w = tid >> 5;

    {
        const uint4* src = (const uint4*)(g_ghwh + cb * Ee);
        uint4* dst = (uint4*)ghw_sh;
        for (int idx = tid; idx < 512 * 128 * 2 / 16; idx += 1024) dst[idx] = src[idx];
    }
    __syncthreads();

    float* p_w  = p_all  + w * MAXD;
    short* nj_w = nj_all + w * MAXD;
    const uint2* gptr = (const uint2*)ghw_sh;

    for (int ii = 0; ii < 8; ii++) {
        int i = half * 256 + w * 8 + ii;
        int cnt = g_cnt[cb + i];
        float ah1i = g_ah1[cb + i];
        const short* adjr = g_adj + (cb + i) * MAXD;
        float e[4]; short njr[4];
#pragma unroll
        for (int q = 0; q < 4; q++) {
            int idx = lane + 32 * q;
            if (idx < cnt) {
                njr[q] = adjr[idx];
                float x = ah1i + g_ah2[cb + njr[q]];
                e[q] = x > 0.f ? x : 0.2f * x;
            } else { e[q] = -3.0e38f; njr[q] = 0; }
        }
        float m = fmaxf(fmaxf(e[0], e[1]), fmaxf(e[2], e[3]));
#pragma unroll
        for (int off = 16; off; off >>= 1)
            m = fmaxf(m, __shfl_xor_sync(0xffffffffu, m, off));
        float p[4]; float s = 0.f;
#pragma unroll
        for (int q = 0; q < 4; q++) {
            p[q] = (lane + 32 * q < cnt) ? __expf(e[q] - m) : 0.f;
            s += p[q];
        }
#pragma unroll
        for (int off = 16; off; off >>= 1)
            s += __shfl_xor_sync(0xffffffffu, s, off);
        float inv = cnt > 0 ? 1.f / s : 0.f;
#pragma unroll
        for (int q = 0; q < 4; q++) {
            p_w[lane + 32 * q]  = p[q] * inv;
            nj_w[lane + 32 * q] = njr[q];
        }
        __syncwarp();
        float4 acc = make_float4(0.f, 0.f, 0.f, 0.f);
#pragma unroll 2
        for (int j = 0; j < cnt; j++) {
            int nj = nj_w[j];
            float pj = p_w[j];
            uint2 hv = gptr[nj * 32 + lane];
            float2 f01 = __half22float2(*reinterpret_cast<__half2*>(&hv.x));
            float2 f23 = __half22float2(*reinterpret_cast<__half2*>(&hv.y));
            acc.x = fmaf(pj, f01.x, acc.x);
            acc.y = fmaf(pj, f01.y, acc.y);
            acc.z = fmaf(pj, f23.x, acc.z);
            acc.w = fmaf(pj, f23.y, acc.w);
        }
        float4 wc = *(const float4*)(whc + (cb + i) * Ee + 4 * lane);
        float4 v;
        v.x = wc.x + acc.x; v.y = wc.y + acc.y;
        v.z = wc.z + acc.z; v.w = wc.w + acc.w;
        v.x = v.x > 0.f ? v.x : expm1f(v.x);
        v.y = v.y > 0.f ? v.y : expm1f(v.y);
        v.z = v.z > 0.f ? v.z : expm1f(v.z);
        v.w = v.w > 0.f ? v.w : expm1f(v.w);
        *(float4*)(whn + (cb + i) * Ee + 4 * lane) = v;
        union { __half2 h[2]; uint2 u; } cv;
        cv.h[0] = __float22half2_rn(make_float2(v.x, v.y));
        cv.h[1] = __float22half2_rn(make_float2(v.z, v.w));
        *(uint2*)(whnh + (cb + i) * Ee + 4 * lane) = cv.u;
        __syncwarp();
    }
}

// ---------------- two-stage reduce + output projection -------------------
__global__ void __launch_bounds__(128)
k_reduce1()
{
    int b = blockIdx.x, g = blockIdx.y, s = blockIdx.z;   // s: node slice 0..7
    int tid = threadIdx.x;
    const float* f = g_chB + (((size_t)(2 * g)     * Bz + b) * Nn + s * 64) * Ee;
    const float* r = g_chB + (((size_t)(2 * g + 1) * Bz + b) * Nn + s * 64) * Ee;
    float acc = 0.f;
#pragma unroll 8
    for (int n = 0; n < 64; n++)
        acc += f[(size_t)n * Ee + tid] + r[(size_t)n * Ee + tid];
    g_part[(((size_t)g * Bz + b) * 8 + s) * Ee + tid] = acc;
}

__global__ void __launch_bounds__(128)
k_reduce2(const float* __restrict__ Wout, const float* __restrict__ bout)
{
    int b = blockIdx.x, g = blockIdx.y;
    int tid = threadIdx.x;
    __shared__ float mid[128];
    const float* pp = g_part + ((size_t)g * Bz + b) * 8 * Ee;
    float s = 0.f;
#pragma unroll
    for (int k = 0; k < 8; k++) s += pp[k * Ee + tid];
    mid[tid] = s;
    __syncthreads();
    if (tid < OUTD) {
        float acc = bout[tid];
#pragma unroll 8
        for (int e = 0; e < Ee; e++)
            acc = fmaf(mid[e], __ldg(&Wout[e * OUTD + tid]), acc);
        g_emb[((size_t)g * Bz + b) * OUTD + tid] = acc;
    }
}

// ---------------- cosine similarity -> (1+cos)/2 -------------------------
__global__ void k_cos(float* __restrict__ out)
{
    int b = blockIdx.x;
    int tid = threadIdx.x, lane = tid & 31, w = tid >> 5;
    float x1 = g_emb[(size_t)b * OUTD + tid];
    float x2 = g_emb[(size_t)(Bz + b) * OUTD + tid];
    float d = x1 * x2, n1 = x1 * x1, n2 = x2 * x2;
#pragma unroll
    for (int off = 16; off; off >>= 1) {
        d  += __shfl_xor_sync(0xffffffffu, d,  off);
        n1 += __shfl_xor_sync(0xffffffffu, n1, off);
        n2 += __shfl_xor_sync(0xffffffffu, n2, off);
    }
    __shared__ float sh[6];
    if (lane == 0) { sh[w * 3] = d; sh[w * 3 + 1] = n1; sh[w * 3 + 2] = n2; }
    __syncthreads();
    if (tid == 0) {
        float dd = sh[0] + sh[3], a = sh[1] + sh[4], c2 = sh[2] + sh[5];
        float denom = fmaxf(sqrtf(a), 1e-12f) * fmaxf(sqrtf(c2), 1e-12f);
        out[b] = 0.5f * (1.f + dd / denom);
    }
}

// ---------------- launch sequence ----------------------------------------
extern "C" void kernel_launch(void* const* d_in, const int* in_sizes, int n_in,
                              void* d_out, int out_size)
{
    const float* CFG1 = (const float*)d_in[0];
    const float* LIT1 = (const float*)d_in[2];
    const float* SEM1 = (const float*)d_in[3];
    const float* CFG2 = (const float*)d_in[4];
    const float* LIT2 = (const float*)d_in[6];
    const float* SEM2 = (const float*)d_in[7];
    const float* Wl1  = (const float*)d_in[8];
    const float* gk1  = (const float*)d_in[9];
    const float* grk1 = (const float*)d_in[10];
    const float* gb1  = (const float*)d_in[11];
    const float* Wl2  = (const float*)d_in[12];
    const float* gk2  = (const float*)d_in[13];
    const float* grk2 = (const float*)d_in[14];
    const float* gb2  = (const float*)d_in[15];
    const float* a1w  = (const float*)d_in[16];
    const float* a1b  = (const float*)d_in[17];
    const float* a2w  = (const float*)d_in[18];
    const float* a2b  = (const float*)d_in[19];
    const float* Wg   = (const float*)d_in[20];
    const float* Wout = (const float*)d_in[21];
    const float* bout = (const float*)d_in[22];

    cudaFuncSetAttribute(k_transform, cudaFuncAttributeMaxDynamicSharedMemorySize, TR_SMEM);
    cudaFuncSetAttribute(k_attend,    cudaFuncAttributeMaxDynamicSharedMemorySize, ATT_SMEM);

    k_prep<<<16, 1024>>>(Wg);
    k_build_fwd<<<dim3(64, 32, 2), 256>>>(CFG1, CFG2);
    k_build_rev<<<dim3(2, 32, 2), 256>>>();
    k_lit<<<dim3(16, 32, 2), 256>>>(LIT1, LIT2, Wl1, Wl2);
    k_xp <<<dim3(16, 32, 2), 192>>>(SEM1, SEM2, gk1, gk2, gb1, gb2);
    k_gru<<<64, 192>>>(grk1, grk2, gb1, gb2);

    int srcA = 1;
    for (int s = 0; s < 3; s++) {
        k_transform<<<dim3(8, 32, 4), 256, TR_SMEM>>>(srcA, a1w, a1b, a2w, a2b);
        k_attend   <<<dim3(32, 4, 2), 1024, ATT_SMEM>>>(srcA);
        srcA ^= 1;
    }
    k_reduce1<<<dim3(32, 2, 8), 128>>>();
    k_reduce2<<<dim3(32, 2), 128>>>(Wout, bout);
    k_cos<<<32, 64>>>((float*)d_out);
}